// round 1
// baseline (speedup 1.0000x reference)
#include <cuda_runtime.h>
#include <cstdint>

// Problem constants (fixed shapes)
#define T_TOK 4096
#define HDIM  1024
#define FDIM  4096
#define EDIM  8
#define BM 128
#define BN 128
#define BK 16
#define PADROWS 9216   // 8192 + 8*128 worst-case segment padding

// ---------------- scratch (static device globals; no allocation) ----------
__device__ __align__(16) float g_h[(size_t)PADROWS * FDIM];   // gate_up output (weighted)
__device__ __align__(16) float g_y[(size_t)PADROWS * HDIM];   // down output
__device__ int   g_perm_token[PADROWS];
__device__ float g_perm_weight[PADROWS];
__device__ int   g_token_pos[T_TOK * 2];
__device__ int   g_te[T_TOK * 2];
__device__ float g_tw[T_TOK * 2];
__device__ int   g_counts[EDIM];
__device__ int   g_cursor[EDIM];
__device__ int   g_off[EDIM + 1];

// ---------------- helpers ---------------------------------------------------
__device__ __forceinline__ uint32_t f2tf32(float f) {
    uint32_t u;
    asm("cvt.rna.tf32.f32 %0, %1;" : "=r"(u) : "f"(f));
    return u;
}

__device__ __forceinline__ void mma_tf32(float c[4], const uint32_t a[4],
                                         uint32_t b0, uint32_t b1) {
    asm volatile(
        "mma.sync.aligned.m16n8k8.row.col.f32.tf32.tf32.f32 "
        "{%0,%1,%2,%3}, {%4,%5,%6,%7}, {%8,%9}, {%0,%1,%2,%3};\n"
        : "+f"(c[0]), "+f"(c[1]), "+f"(c[2]), "+f"(c[3])
        : "r"(a[0]), "r"(a[1]), "r"(a[2]), "r"(a[3]), "r"(b0), "r"(b1));
}

// ---------------- init: zero counts, poison permutation ---------------------
__global__ void init_kernel() {
    int i = blockIdx.x * blockDim.x + threadIdx.x;
    if (i < PADROWS) {
        g_perm_token[i] = -1;
        g_perm_weight[i] = 0.f;
    }
    if (i < EDIM) g_counts[i] = 0;
}

// ---------------- router: logits + softmax top2 -----------------------------
__global__ void __launch_bounds__(128) router_kernel(
    const float* __restrict__ x, const float* __restrict__ gw,
    float* __restrict__ logits_out) {
    __shared__ float sgw[EDIM * HDIM];   // 32 KB
    int tid = threadIdx.x;
    for (int i = tid; i < EDIM * HDIM; i += 128) sgw[i] = gw[i];
    __syncthreads();

    int warp = tid >> 5, lane = tid & 31;
    int t = blockIdx.x * 4 + warp;
    const float* xr = x + (size_t)t * HDIM;

    float acc[EDIM];
#pragma unroll
    for (int e = 0; e < EDIM; e++) acc[e] = 0.f;
    for (int j = lane; j < HDIM; j += 32) {
        float xv = xr[j];
#pragma unroll
        for (int e = 0; e < EDIM; e++) acc[e] = fmaf(xv, sgw[e * HDIM + j], acc[e]);
    }
#pragma unroll
    for (int e = 0; e < EDIM; e++)
#pragma unroll
        for (int o = 16; o > 0; o >>= 1)
            acc[e] += __shfl_xor_sync(0xffffffffu, acc[e], o);

    if (lane == 0) {
#pragma unroll
        for (int e = 0; e < EDIM; e++) logits_out[t * EDIM + e] = acc[e];
        // top-2 (strict > keeps lowest index on ties, matching lax.top_k)
        int e0 = 0; float l0 = acc[0];
#pragma unroll
        for (int e = 1; e < EDIM; e++) if (acc[e] > l0) { l0 = acc[e]; e0 = e; }
        int e1 = -1; float l1 = -3.4e38f;
#pragma unroll
        for (int e = 0; e < EDIM; e++)
            if (e != e0 && acc[e] > l1) { l1 = acc[e]; e1 = e; }
        float r = expf(l1 - l0);            // <= 1
        float w0 = 1.f / (1.f + r);
        float w1 = r / (1.f + r);
        g_te[t * 2 + 0] = e0; g_tw[t * 2 + 0] = w0;
        g_te[t * 2 + 1] = e1; g_tw[t * 2 + 1] = w1;
        atomicAdd(&g_counts[e0], 1);
        atomicAdd(&g_counts[e1], 1);
    }
}

// ---------------- scan: padded segment offsets -------------------------------
__global__ void scan_kernel() {
    int off = 0;
    for (int e = 0; e < EDIM; e++) {
        g_off[e] = off;
        g_cursor[e] = off;
        off += ((g_counts[e] + BM - 1) / BM) * BM;
    }
    g_off[EDIM] = off;
}

// ---------------- scatter: build permuted (token,weight) list ----------------
__global__ void scatter_kernel() {
    int t = blockIdx.x * blockDim.x + threadIdx.x;
    if (t >= T_TOK) return;
#pragma unroll
    for (int k = 0; k < 2; k++) {
        int e = g_te[t * 2 + k];
        int pos = atomicAdd(&g_cursor[e], 1);
        g_perm_token[pos] = t;
        g_perm_weight[pos] = g_tw[t * 2 + k];
        g_token_pos[t * 2 + k] = pos;
    }
}

// ---------------- GEMM1: h = silu(x@w1^T) * (x@w3^T) * route_w ---------------
__global__ void __launch_bounds__(512, 1) gemm1_kernel(
    const float* __restrict__ x, const float* __restrict__ gup) {
    int m0 = blockIdx.x * BM;
    if (m0 >= g_off[EDIM]) return;
    int n0 = blockIdx.y * BN;
    int e = 0;
    while (m0 >= g_off[e + 1]) e++;

    __shared__ uint32_t As[BM][BK + 4];      // stride 20: conflict-free frag loads
    __shared__ uint32_t Bs[2][BN][BK + 4];

    int tid = threadIdx.x;
    int lr = tid >> 2;            // 0..127 : load row
    int lc = (tid & 3) * 4;       // load col (float4)
    int tok = g_perm_token[m0 + lr];
    const float* arow = (tok >= 0) ? (x + (size_t)tok * HDIM) : nullptr;
    const float* b1row = gup + ((size_t)e * 2 * FDIM + (n0 + lr)) * HDIM;
    const float* b3row = gup + ((size_t)e * 2 * FDIM + FDIM + (n0 + lr)) * HDIM;

    int warp = tid >> 5, lane = tid & 31;
    int gid = lane >> 2, tig = lane & 3;
    int wm = (warp & 3) * 32, wn = (warp >> 2) * 32;

    float acc[2][2][4][4];
#pragma unroll
    for (int g = 0; g < 2; g++)
#pragma unroll
        for (int mt = 0; mt < 2; mt++)
#pragma unroll
            for (int nt = 0; nt < 4; nt++)
#pragma unroll
                for (int i = 0; i < 4; i++) acc[g][mt][nt][i] = 0.f;

    for (int k0 = 0; k0 < HDIM; k0 += BK) {
        __syncthreads();
        float4 av = arow ? *(const float4*)(arow + k0 + lc)
                         : make_float4(0.f, 0.f, 0.f, 0.f);
        float4 b1v = *(const float4*)(b1row + k0 + lc);
        float4 b3v = *(const float4*)(b3row + k0 + lc);
        As[lr][lc + 0] = f2tf32(av.x);  As[lr][lc + 1] = f2tf32(av.y);
        As[lr][lc + 2] = f2tf32(av.z);  As[lr][lc + 3] = f2tf32(av.w);
        Bs[0][lr][lc + 0] = f2tf32(b1v.x); Bs[0][lr][lc + 1] = f2tf32(b1v.y);
        Bs[0][lr][lc + 2] = f2tf32(b1v.z); Bs[0][lr][lc + 3] = f2tf32(b1v.w);
        Bs[1][lr][lc + 0] = f2tf32(b3v.x); Bs[1][lr][lc + 1] = f2tf32(b3v.y);
        Bs[1][lr][lc + 2] = f2tf32(b3v.z); Bs[1][lr][lc + 3] = f2tf32(b3v.w);
        __syncthreads();

#pragma unroll
        for (int kk = 0; kk < BK; kk += 8) {
            uint32_t a[2][4];
#pragma unroll
            for (int mt = 0; mt < 2; mt++) {
                int r = wm + mt * 16 + gid;
                a[mt][0] = As[r][kk + tig];
                a[mt][1] = As[r + 8][kk + tig];
                a[mt][2] = As[r][kk + tig + 4];
                a[mt][3] = As[r + 8][kk + tig + 4];
            }
#pragma unroll
            for (int g = 0; g < 2; g++) {
#pragma unroll
                for (int nt = 0; nt < 4; nt++) {
                    int n = wn + nt * 8 + gid;
                    uint32_t b0 = Bs[g][n][kk + tig];
                    uint32_t b1 = Bs[g][n][kk + tig + 4];
                    mma_tf32(acc[g][0][nt], a[0], b0, b1);
                    mma_tf32(acc[g][1][nt], a[1], b0, b1);
                }
            }
        }
    }

    // epilogue: silu(gate) * up * routing_weight
#pragma unroll
    for (int mt = 0; mt < 2; mt++) {
        int rbase = m0 + wm + mt * 16 + gid;
        float wA = g_perm_weight[rbase];
        float wB = g_perm_weight[rbase + 8];
#pragma unroll
        for (int nt = 0; nt < 4; nt++) {
            int cbase = n0 + wn + nt * 8 + 2 * tig;
#pragma unroll
            for (int i = 0; i < 4; i++) {
                float gv = acc[0][mt][nt][i];
                float uv = acc[1][mt][nt][i];
                float hv = (gv / (1.f + expf(-gv))) * uv;
                int row = rbase + ((i >> 1) ? 8 : 0);
                int col = cbase + (i & 1);
                float wgt = (i >> 1) ? wB : wA;
                g_h[(size_t)row * FDIM + col] = hv * wgt;
            }
        }
    }
}

// ---------------- GEMM2: y = h @ w2^T ----------------------------------------
__global__ void __launch_bounds__(512, 1) gemm2_kernel(
    const float* __restrict__ dw) {
    int m0 = blockIdx.x * BM;
    if (m0 >= g_off[EDIM]) return;
    int n0 = blockIdx.y * BN;   // over HDIM
    int e = 0;
    while (m0 >= g_off[e + 1]) e++;

    __shared__ uint32_t As[BM][BK + 4];
    __shared__ uint32_t Bs[BN][BK + 4];

    int tid = threadIdx.x;
    int lr = tid >> 2;
    int lc = (tid & 3) * 4;
    const float* arow = g_h + (size_t)(m0 + lr) * FDIM;
    const float* brow = dw + ((size_t)e * HDIM + (n0 + lr)) * FDIM;

    int warp = tid >> 5, lane = tid & 31;
    int gid = lane >> 2, tig = lane & 3;
    int wm = (warp & 3) * 32, wn = (warp >> 2) * 32;

    float acc[2][4][4];
#pragma unroll
    for (int mt = 0; mt < 2; mt++)
#pragma unroll
        for (int nt = 0; nt < 4; nt++)
#pragma unroll
            for (int i = 0; i < 4; i++) acc[mt][nt][i] = 0.f;

    for (int k0 = 0; k0 < FDIM; k0 += BK) {
        __syncthreads();
        float4 av = *(const float4*)(arow + k0 + lc);
        float4 bv = *(const float4*)(brow + k0 + lc);
        As[lr][lc + 0] = f2tf32(av.x);  As[lr][lc + 1] = f2tf32(av.y);
        As[lr][lc + 2] = f2tf32(av.z);  As[lr][lc + 3] = f2tf32(av.w);
        Bs[lr][lc + 0] = f2tf32(bv.x);  Bs[lr][lc + 1] = f2tf32(bv.y);
        Bs[lr][lc + 2] = f2tf32(bv.z);  Bs[lr][lc + 3] = f2tf32(bv.w);
        __syncthreads();

#pragma unroll
        for (int kk = 0; kk < BK; kk += 8) {
            uint32_t a[2][4];
#pragma unroll
            for (int mt = 0; mt < 2; mt++) {
                int r = wm + mt * 16 + gid;
                a[mt][0] = As[r][kk + tig];
                a[mt][1] = As[r + 8][kk + tig];
                a[mt][2] = As[r][kk + tig + 4];
                a[mt][3] = As[r + 8][kk + tig + 4];
            }
#pragma unroll
            for (int nt = 0; nt < 4; nt++) {
                int n = wn + nt * 8 + gid;
                uint32_t b0 = Bs[n][kk + tig];
                uint32_t b1 = Bs[n][kk + tig + 4];
                mma_tf32(acc[0][nt], a[0], b0, b1);
                mma_tf32(acc[1][nt], a[1], b0, b1);
            }
        }
    }

#pragma unroll
    for (int mt = 0; mt < 2; mt++) {
        int rbase = m0 + wm + mt * 16 + gid;
#pragma unroll
        for (int nt = 0; nt < 4; nt++) {
            int cbase = n0 + wn + nt * 8 + 2 * tig;
#pragma unroll
            for (int i = 0; i < 4; i++) {
                int row = rbase + ((i >> 1) ? 8 : 0);
                int col = cbase + (i & 1);
                g_y[(size_t)row * HDIM + col] = acc[mt][nt][i];
            }
        }
    }
}

// ---------------- combine: out[t] = y[pos0] + y[pos1] ------------------------
__global__ void combine_kernel(float* __restrict__ out) {
    int i = blockIdx.x * blockDim.x + threadIdx.x;
    if (i >= T_TOK * HDIM) return;
    int t = i >> 10, n = i & (HDIM - 1);
    int p0 = g_token_pos[t * 2 + 0];
    int p1 = g_token_pos[t * 2 + 1];
    out[i] = g_y[(size_t)p0 * HDIM + n] + g_y[(size_t)p1 * HDIM + n];
}

// ---------------- launcher ----------------------------------------------------
extern "C" void kernel_launch(void* const* d_in, const int* in_sizes, int n_in,
                              void* d_out, int out_size) {
    const float* x   = (const float*)d_in[0];   // (2,2048,1024)
    const float* gw  = (const float*)d_in[1];   // (8,1024)
    const float* gup = (const float*)d_in[2];   // (8,8192,1024)
    const float* dw  = (const float*)d_in[3];   // (8,1024,4096)
    float* out = (float*)d_out;                 // out (4194304) ++ logits (32768)
    float* logits = out + (size_t)T_TOK * HDIM;

    init_kernel<<<(PADROWS + 255) / 256, 256>>>();
    router_kernel<<<T_TOK / 4, 128>>>(x, gw, logits);
    scan_kernel<<<1, 1>>>();
    scatter_kernel<<<(T_TOK + 255) / 256, 256>>>();
    gemm1_kernel<<<dim3(PADROWS / BM, FDIM / BN), 512>>>(x, gup);
    gemm2_kernel<<<dim3(PADROWS / BM, HDIM / BN), 512>>>(dw);
    combine_kernel<<<(T_TOK * HDIM) / 256, 256>>>(out);
    (void)in_sizes; (void)n_in; (void)out_size;
}

// round 2
// speedup vs baseline: 1.6485x; 1.6485x over previous
#include <cuda_runtime.h>
#include <cstdint>

// Problem constants (fixed shapes)
#define T_TOK 4096
#define HDIM  1024
#define FDIM  4096
#define EDIM  8
#define BM 128
#define BN 128
#define BK 32
#define LDN 36          // smem row stride (words): 4r mod 32 -> conflict-free
#define PADROWS 9216    // 8192 + 8*128 worst-case segment padding

// ---------------- scratch (static device globals; no allocation) ----------
__device__ __align__(16) float g_h[(size_t)PADROWS * FDIM];   // gate_up output (weighted)
__device__ __align__(16) float g_y[(size_t)PADROWS * HDIM];   // down output
__device__ int   g_perm_token[PADROWS];
__device__ float g_perm_weight[PADROWS];
__device__ int   g_token_pos[T_TOK * 2];
__device__ int   g_te[T_TOK * 2];
__device__ float g_tw[T_TOK * 2];
__device__ int   g_counts[EDIM];
__device__ int   g_cursor[EDIM];
__device__ int   g_off[EDIM + 1];

// ---------------- helpers ---------------------------------------------------
__device__ __forceinline__ uint32_t f2tf32(float f) {
    uint32_t u;
    asm("cvt.rna.tf32.f32 %0, %1;" : "=r"(u) : "f"(f));
    return u;
}

__device__ __forceinline__ void st_tf32x4(uint32_t* p, float4 v) {
    p[0] = f2tf32(v.x); p[1] = f2tf32(v.y);
    p[2] = f2tf32(v.z); p[3] = f2tf32(v.w);
}

__device__ __forceinline__ void mma_tf32(float c[4], const uint32_t a[4],
                                         uint32_t b0, uint32_t b1) {
    asm volatile(
        "mma.sync.aligned.m16n8k8.row.col.f32.tf32.tf32.f32 "
        "{%0,%1,%2,%3}, {%4,%5,%6,%7}, {%8,%9}, {%0,%1,%2,%3};\n"
        : "+f"(c[0]), "+f"(c[1]), "+f"(c[2]), "+f"(c[3])
        : "r"(a[0]), "r"(a[1]), "r"(a[2]), "r"(a[3]), "r"(b0), "r"(b1));
}

// ---------------- init: zero counts, poison permutation ---------------------
__global__ void init_kernel() {
    int i = blockIdx.x * blockDim.x + threadIdx.x;
    if (i < PADROWS) {
        g_perm_token[i] = -1;
        g_perm_weight[i] = 0.f;
    }
    if (i < EDIM) g_counts[i] = 0;
}

// ---------------- router: logits + softmax top2 -----------------------------
__global__ void __launch_bounds__(128) router_kernel(
    const float* __restrict__ x, const float* __restrict__ gw,
    float* __restrict__ logits_out) {
    __shared__ float sgw[EDIM * HDIM];   // 32 KB
    int tid = threadIdx.x;
    for (int i = tid; i < EDIM * HDIM; i += 128) sgw[i] = gw[i];
    __syncthreads();

    int warp = tid >> 5, lane = tid & 31;
    int t = blockIdx.x * 4 + warp;
    const float* xr = x + (size_t)t * HDIM;

    float acc[EDIM];
#pragma unroll
    for (int e = 0; e < EDIM; e++) acc[e] = 0.f;
    for (int j = lane; j < HDIM; j += 32) {
        float xv = xr[j];
#pragma unroll
        for (int e = 0; e < EDIM; e++) acc[e] = fmaf(xv, sgw[e * HDIM + j], acc[e]);
    }
#pragma unroll
    for (int e = 0; e < EDIM; e++)
#pragma unroll
        for (int o = 16; o > 0; o >>= 1)
            acc[e] += __shfl_xor_sync(0xffffffffu, acc[e], o);

    if (lane == 0) {
#pragma unroll
        for (int e = 0; e < EDIM; e++) logits_out[t * EDIM + e] = acc[e];
        // top-2 (strict > keeps lowest index on ties, matching lax.top_k)
        int e0 = 0; float l0 = acc[0];
#pragma unroll
        for (int e = 1; e < EDIM; e++) if (acc[e] > l0) { l0 = acc[e]; e0 = e; }
        int e1 = -1; float l1 = -3.4e38f;
#pragma unroll
        for (int e = 0; e < EDIM; e++)
            if (e != e0 && acc[e] > l1) { l1 = acc[e]; e1 = e; }
        float r = expf(l1 - l0);            // <= 1
        float w0 = 1.f / (1.f + r);
        float w1 = r / (1.f + r);
        g_te[t * 2 + 0] = e0; g_tw[t * 2 + 0] = w0;
        g_te[t * 2 + 1] = e1; g_tw[t * 2 + 1] = w1;
        atomicAdd(&g_counts[e0], 1);
        atomicAdd(&g_counts[e1], 1);
    }
}

// ---------------- scan: padded segment offsets -------------------------------
__global__ void scan_kernel() {
    int off = 0;
    for (int e = 0; e < EDIM; e++) {
        g_off[e] = off;
        g_cursor[e] = off;
        off += ((g_counts[e] + BM - 1) / BM) * BM;
    }
    g_off[EDIM] = off;
}

// ---------------- scatter: build permuted (token,weight) list ----------------
__global__ void scatter_kernel() {
    int t = blockIdx.x * blockDim.x + threadIdx.x;
    if (t >= T_TOK) return;
#pragma unroll
    for (int k = 0; k < 2; k++) {
        int e = g_te[t * 2 + k];
        int pos = atomicAdd(&g_cursor[e], 1);
        g_perm_token[pos] = t;
        g_perm_weight[pos] = g_tw[t * 2 + k];
        g_token_pos[t * 2 + k] = pos;
    }
}

// ---------------- GEMM1: h = silu(x@w1^T) * (x@w3^T) * route_w ---------------
// Double-buffered smem + register prefetch; one __syncthreads per K-slab.
__global__ void __launch_bounds__(512, 1) gemm1_kernel(
    const float* __restrict__ x, const float* __restrict__ gup) {
    extern __shared__ uint32_t sm1[];
    // layout: As[2][BM][LDN], then Bs[2][2][BN][LDN]
    uint32_t (*As)[BM][LDN] = (uint32_t (*)[BM][LDN])sm1;
    uint32_t (*Bs)[2][BN][LDN] = (uint32_t (*)[2][BN][LDN])(sm1 + 2 * BM * LDN);

    int m0 = blockIdx.x * BM;
    if (m0 >= g_off[EDIM]) return;
    int n0 = blockIdx.y * BN;
    int e = 0;
    while (m0 >= g_off[e + 1]) e++;

    int tid = threadIdx.x;
    int lr = tid >> 3;            // 0..63  (row, pass 0)
    int lc = (tid & 7) * 4;       // 0..28  (col, float4)
    int tok0 = g_perm_token[m0 + lr];
    int tok1 = g_perm_token[m0 + lr + 64];
    const float* a0 = (tok0 >= 0) ? (x + (size_t)tok0 * HDIM) : nullptr;
    const float* a1 = (tok1 >= 0) ? (x + (size_t)tok1 * HDIM) : nullptr;
    const float* b1r0 = gup + ((size_t)e * 2 * FDIM + (n0 + lr)) * HDIM;
    const float* b1r1 = b1r0 + (size_t)64 * HDIM;
    const float* b3r0 = b1r0 + (size_t)FDIM * HDIM;
    const float* b3r1 = b3r0 + (size_t)64 * HDIM;

    int warp = tid >> 5, lane = tid & 31;
    int gid = lane >> 2, tig = lane & 3;
    int wm = (warp & 3) * 32, wn = (warp >> 2) * 32;

    float acc[2][2][4][4];
#pragma unroll
    for (int g = 0; g < 2; g++)
#pragma unroll
        for (int mt = 0; mt < 2; mt++)
#pragma unroll
            for (int nt = 0; nt < 4; nt++)
#pragma unroll
                for (int i = 0; i < 4; i++) acc[g][mt][nt][i] = 0.f;

    const float4 f4z = make_float4(0.f, 0.f, 0.f, 0.f);
    float4 pa0, pa1, pb10, pb11, pb30, pb31;

    // prefetch first slab
    pa0 = a0 ? *(const float4*)(a0 + lc) : f4z;
    pa1 = a1 ? *(const float4*)(a1 + lc) : f4z;
    pb10 = *(const float4*)(b1r0 + lc);
    pb11 = *(const float4*)(b1r1 + lc);
    pb30 = *(const float4*)(b3r0 + lc);
    pb31 = *(const float4*)(b3r1 + lc);

    int buf = 0;
    for (int k0 = 0; k0 < HDIM; k0 += BK) {
        // commit prefetched slab to smem[buf]
        st_tf32x4(&As[buf][lr][lc], pa0);
        st_tf32x4(&As[buf][lr + 64][lc], pa1);
        st_tf32x4(&Bs[buf][0][lr][lc], pb10);
        st_tf32x4(&Bs[buf][0][lr + 64][lc], pb11);
        st_tf32x4(&Bs[buf][1][lr][lc], pb30);
        st_tf32x4(&Bs[buf][1][lr + 64][lc], pb31);
        __syncthreads();

        int kn = k0 + BK;
        if (kn < HDIM) {   // prefetch next slab (LDGs overlap the MMAs below)
            pa0 = a0 ? *(const float4*)(a0 + kn + lc) : f4z;
            pa1 = a1 ? *(const float4*)(a1 + kn + lc) : f4z;
            pb10 = *(const float4*)(b1r0 + kn + lc);
            pb11 = *(const float4*)(b1r1 + kn + lc);
            pb30 = *(const float4*)(b3r0 + kn + lc);
            pb31 = *(const float4*)(b3r1 + kn + lc);
        }

#pragma unroll
        for (int kk = 0; kk < BK; kk += 8) {
            uint32_t a[2][4];
#pragma unroll
            for (int mt = 0; mt < 2; mt++) {
                int r = wm + mt * 16 + gid;
                a[mt][0] = As[buf][r][kk + tig];
                a[mt][1] = As[buf][r + 8][kk + tig];
                a[mt][2] = As[buf][r][kk + tig + 4];
                a[mt][3] = As[buf][r + 8][kk + tig + 4];
            }
#pragma unroll
            for (int g = 0; g < 2; g++) {
#pragma unroll
                for (int nt = 0; nt < 4; nt++) {
                    int n = wn + nt * 8 + gid;
                    uint32_t b0 = Bs[buf][g][n][kk + tig];
                    uint32_t b1 = Bs[buf][g][n][kk + tig + 4];
                    mma_tf32(acc[g][0][nt], a[0], b0, b1);
                    mma_tf32(acc[g][1][nt], a[1], b0, b1);
                }
            }
        }
        buf ^= 1;
    }

    // epilogue: silu(gate) * up * routing_weight
#pragma unroll
    for (int mt = 0; mt < 2; mt++) {
        int rbase = m0 + wm + mt * 16 + gid;
        float wA = g_perm_weight[rbase];
        float wB = g_perm_weight[rbase + 8];
#pragma unroll
        for (int nt = 0; nt < 4; nt++) {
            int cbase = n0 + wn + nt * 8 + 2 * tig;
#pragma unroll
            for (int i = 0; i < 4; i++) {
                float gv = acc[0][mt][nt][i];
                float uv = acc[1][mt][nt][i];
                float hv = (gv / (1.f + expf(-gv))) * uv;
                int row = rbase + ((i >> 1) ? 8 : 0);
                int col = cbase + (i & 1);
                float wgt = (i >> 1) ? wB : wA;
                g_h[(size_t)row * FDIM + col] = hv * wgt;
            }
        }
    }
}

// ---------------- GEMM2: y = h @ w2^T ----------------------------------------
__global__ void __launch_bounds__(512, 1) gemm2_kernel(
    const float* __restrict__ dw) {
    extern __shared__ uint32_t sm2[];
    uint32_t (*As)[BM][LDN] = (uint32_t (*)[BM][LDN])sm2;
    uint32_t (*Bs)[BN][LDN] = (uint32_t (*)[BN][LDN])(sm2 + 2 * BM * LDN);

    int m0 = blockIdx.x * BM;
    if (m0 >= g_off[EDIM]) return;
    int n0 = blockIdx.y * BN;   // over HDIM
    int e = 0;
    while (m0 >= g_off[e + 1]) e++;

    int tid = threadIdx.x;
    int lr = tid >> 3;
    int lc = (tid & 7) * 4;
    const float* a0 = g_h + (size_t)(m0 + lr) * FDIM;
    const float* a1 = a0 + (size_t)64 * FDIM;
    const float* b0p = dw + ((size_t)e * HDIM + (n0 + lr)) * FDIM;
    const float* b1p = b0p + (size_t)64 * FDIM;

    int warp = tid >> 5, lane = tid & 31;
    int gid = lane >> 2, tig = lane & 3;
    int wm = (warp & 3) * 32, wn = (warp >> 2) * 32;

    float acc[2][4][4];
#pragma unroll
    for (int mt = 0; mt < 2; mt++)
#pragma unroll
        for (int nt = 0; nt < 4; nt++)
#pragma unroll
            for (int i = 0; i < 4; i++) acc[mt][nt][i] = 0.f;

    float4 pa0, pa1, pb0, pb1;
    pa0 = *(const float4*)(a0 + lc);
    pa1 = *(const float4*)(a1 + lc);
    pb0 = *(const float4*)(b0p + lc);
    pb1 = *(const float4*)(b1p + lc);

    int buf = 0;
    for (int k0 = 0; k0 < FDIM; k0 += BK) {
        st_tf32x4(&As[buf][lr][lc], pa0);
        st_tf32x4(&As[buf][lr + 64][lc], pa1);
        st_tf32x4(&Bs[buf][lr][lc], pb0);
        st_tf32x4(&Bs[buf][lr + 64][lc], pb1);
        __syncthreads();

        int kn = k0 + BK;
        if (kn < FDIM) {
            pa0 = *(const float4*)(a0 + kn + lc);
            pa1 = *(const float4*)(a1 + kn + lc);
            pb0 = *(const float4*)(b0p + kn + lc);
            pb1 = *(const float4*)(b1p + kn + lc);
        }

#pragma unroll
        for (int kk = 0; kk < BK; kk += 8) {
            uint32_t a[2][4];
#pragma unroll
            for (int mt = 0; mt < 2; mt++) {
                int r = wm + mt * 16 + gid;
                a[mt][0] = As[buf][r][kk + tig];
                a[mt][1] = As[buf][r + 8][kk + tig];
                a[mt][2] = As[buf][r][kk + tig + 4];
                a[mt][3] = As[buf][r + 8][kk + tig + 4];
            }
#pragma unroll
            for (int nt = 0; nt < 4; nt++) {
                int n = wn + nt * 8 + gid;
                uint32_t b0 = Bs[buf][n][kk + tig];
                uint32_t b1 = Bs[buf][n][kk + tig + 4];
                mma_tf32(acc[0][nt], a[0], b0, b1);
                mma_tf32(acc[1][nt], a[1], b0, b1);
            }
        }
        buf ^= 1;
    }

#pragma unroll
    for (int mt = 0; mt < 2; mt++) {
        int rbase = m0 + wm + mt * 16 + gid;
#pragma unroll
        for (int nt = 0; nt < 4; nt++) {
            int cbase = n0 + wn + nt * 8 + 2 * tig;
#pragma unroll
            for (int i = 0; i < 4; i++) {
                int row = rbase + ((i >> 1) ? 8 : 0);
                int col = cbase + (i & 1);
                g_y[(size_t)row * HDIM + col] = acc[mt][nt][i];
            }
        }
    }
}

// ---------------- combine: out[t] = y[pos0] + y[pos1] ------------------------
__global__ void combine_kernel(float* __restrict__ out) {
    int i = blockIdx.x * blockDim.x + threadIdx.x;
    if (i >= T_TOK * HDIM) return;
    int t = i >> 10, n = i & (HDIM - 1);
    int p0 = g_token_pos[t * 2 + 0];
    int p1 = g_token_pos[t * 2 + 1];
    out[i] = g_y[(size_t)p0 * HDIM + n] + g_y[(size_t)p1 * HDIM + n];
}

// ---------------- launcher ----------------------------------------------------
extern "C" void kernel_launch(void* const* d_in, const int* in_sizes, int n_in,
                              void* d_out, int out_size) {
    const float* x   = (const float*)d_in[0];   // (2,2048,1024)
    const float* gw  = (const float*)d_in[1];   // (8,1024)
    const float* gup = (const float*)d_in[2];   // (8,8192,1024)
    const float* dw  = (const float*)d_in[3];   // (8,1024,4096)
    float* out = (float*)d_out;                 // out (4194304) ++ logits (32768)
    float* logits = out + (size_t)T_TOK * HDIM;

    const int smem1 = (2 * BM * LDN + 2 * 2 * BN * LDN) * 4;   // 110592 B
    const int smem2 = (2 * BM * LDN + 2 * BN * LDN) * 4;       //  73728 B
    cudaFuncSetAttribute(gemm1_kernel, cudaFuncAttributeMaxDynamicSharedMemorySize, smem1);
    cudaFuncSetAttribute(gemm2_kernel, cudaFuncAttributeMaxDynamicSharedMemorySize, smem2);

    init_kernel<<<(PADROWS + 255) / 256, 256>>>();
    router_kernel<<<T_TOK / 4, 128>>>(x, gw, logits);
    scan_kernel<<<1, 1>>>();
    scatter_kernel<<<(T_TOK + 255) / 256, 256>>>();
    gemm1_kernel<<<dim3(PADROWS / BM, FDIM / BN), 512, smem1>>>(x, gup);
    gemm2_kernel<<<dim3(PADROWS / BM, HDIM / BN), 512, smem2>>>(dw);
    combine_kernel<<<(T_TOK * HDIM) / 256, 256>>>(out);
    (void)in_sizes; (void)n_in; (void)out_size;
}

// round 3
// speedup vs baseline: 1.6890x; 1.0246x over previous
#include <cuda_runtime.h>
#include <cstdint>

// Problem constants (fixed shapes)
#define T_TOK 4096
#define HDIM  1024
#define FDIM  4096
#define EDIM  8
#define BM 128
#define BN 128
#define BK 32
#define LDN 36          // smem row stride (words): conflict-free
#define PADROWS 9216    // 8192 + 8*128 worst-case segment padding

// ---------------- scratch (static device globals; no allocation) ----------
__device__ __align__(16) float g_h[(size_t)PADROWS * FDIM];
__device__ __align__(16) float g_y[(size_t)PADROWS * HDIM];
__device__ int   g_perm_token[PADROWS];
__device__ float g_perm_weight[PADROWS];
__device__ int   g_token_pos[T_TOK * 2];
__device__ int   g_te[T_TOK * 2];
__device__ float g_tw[T_TOK * 2];
__device__ int   g_counts[EDIM];
__device__ int   g_cursor[EDIM];
__device__ int   g_off[EDIM + 1];

// ---------------- helpers ---------------------------------------------------
__device__ __forceinline__ uint32_t f2tf32(float f) {
    uint32_t u;
    asm("cvt.rna.tf32.f32 %0, %1;" : "=r"(u) : "f"(f));
    return u;
}

__device__ __forceinline__ void st_tf32x4(uint32_t* p, float4 v) {
    p[0] = f2tf32(v.x); p[1] = f2tf32(v.y);
    p[2] = f2tf32(v.z); p[3] = f2tf32(v.w);
}

__device__ __forceinline__ void mma_tf32(float c[4], const uint32_t a[4],
                                         uint32_t b0, uint32_t b1) {
    asm volatile(
        "mma.sync.aligned.m16n8k8.row.col.f32.tf32.tf32.f32 "
        "{%0,%1,%2,%3}, {%4,%5,%6,%7}, {%8,%9}, {%0,%1,%2,%3};\n"
        : "+f"(c[0]), "+f"(c[1]), "+f"(c[2]), "+f"(c[3])
        : "r"(a[0]), "r"(a[1]), "r"(a[2]), "r"(a[3]), "r"(b0), "r"(b1));
}

// ---------------- init ------------------------------------------------------
__global__ void init_kernel() {
    int i = blockIdx.x * blockDim.x + threadIdx.x;
    if (i < PADROWS) {
        g_perm_token[i] = -1;
        g_perm_weight[i] = 0.f;
    }
    if (i < EDIM) g_counts[i] = 0;
}

// ---------------- router: logits + softmax top2 -----------------------------
__global__ void __launch_bounds__(128) router_kernel(
    const float* __restrict__ x, const float* __restrict__ gw,
    float* __restrict__ logits_out) {
    __shared__ float sgw[EDIM * HDIM];
    int tid = threadIdx.x;
    for (int i = tid; i < EDIM * HDIM; i += 128) sgw[i] = gw[i];
    __syncthreads();

    int warp = tid >> 5, lane = tid & 31;
    int t = blockIdx.x * 4 + warp;
    const float* xr = x + (size_t)t * HDIM;

    float acc[EDIM];
#pragma unroll
    for (int e = 0; e < EDIM; e++) acc[e] = 0.f;
    for (int j = lane; j < HDIM; j += 32) {
        float xv = xr[j];
#pragma unroll
        for (int e = 0; e < EDIM; e++) acc[e] = fmaf(xv, sgw[e * HDIM + j], acc[e]);
    }
#pragma unroll
    for (int e = 0; e < EDIM; e++)
#pragma unroll
        for (int o = 16; o > 0; o >>= 1)
            acc[e] += __shfl_xor_sync(0xffffffffu, acc[e], o);

    if (lane == 0) {
#pragma unroll
        for (int e = 0; e < EDIM; e++) logits_out[t * EDIM + e] = acc[e];
        int e0 = 0; float l0 = acc[0];
#pragma unroll
        for (int e = 1; e < EDIM; e++) if (acc[e] > l0) { l0 = acc[e]; e0 = e; }
        int e1 = -1; float l1 = -3.4e38f;
#pragma unroll
        for (int e = 0; e < EDIM; e++)
            if (e != e0 && acc[e] > l1) { l1 = acc[e]; e1 = e; }
        float r = expf(l1 - l0);
        float w0 = 1.f / (1.f + r);
        float w1 = r / (1.f + r);
        g_te[t * 2 + 0] = e0; g_tw[t * 2 + 0] = w0;
        g_te[t * 2 + 1] = e1; g_tw[t * 2 + 1] = w1;
        atomicAdd(&g_counts[e0], 1);
        atomicAdd(&g_counts[e1], 1);
    }
}

// ---------------- scan ------------------------------------------------------
__global__ void scan_kernel() {
    int off = 0;
    for (int e = 0; e < EDIM; e++) {
        g_off[e] = off;
        g_cursor[e] = off;
        off += ((g_counts[e] + BM - 1) / BM) * BM;
    }
    g_off[EDIM] = off;
}

// ---------------- scatter ---------------------------------------------------
__global__ void scatter_kernel() {
    int t = blockIdx.x * blockDim.x + threadIdx.x;
    if (t >= T_TOK) return;
#pragma unroll
    for (int k = 0; k < 2; k++) {
        int e = g_te[t * 2 + k];
        int pos = atomicAdd(&g_cursor[e], 1);
        g_perm_token[pos] = t;
        g_perm_weight[pos] = g_tw[t * 2 + k];
        g_token_pos[t * 2 + k] = pos;
    }
}

// ---------------- GEMM1: h = silu(x@w1^T) * (x@w3^T) * route_w ---------------
// 256 threads / 8 warps; warp tile 64 rows x (2g x 32) cols; double-buffered.
__global__ void __launch_bounds__(256, 1) gemm1_kernel(
    const float* __restrict__ x, const float* __restrict__ gup) {
    extern __shared__ uint32_t sm1[];
    uint32_t (*As)[BM][LDN] = (uint32_t (*)[BM][LDN])sm1;
    uint32_t (*Bs)[2][BN][LDN] = (uint32_t (*)[2][BN][LDN])(sm1 + 2 * BM * LDN);

    int m0 = blockIdx.x * BM;
    if (m0 >= g_off[EDIM]) return;
    int n0 = blockIdx.y * BN;
    int e = 0;
    while (m0 >= g_off[e + 1]) e++;

    int tid = threadIdx.x;
    int lr = tid >> 3;            // 0..31 (row within pass)
    int lc = (tid & 7) * 4;       // 0..28 (col, float4)

    // A pointers: 4 passes of 32 rows
    const float* ap[4];
#pragma unroll
    for (int p = 0; p < 4; p++) {
        int tok = g_perm_token[m0 + lr + 32 * p];
        ap[p] = (tok >= 0) ? (x + (size_t)tok * HDIM) : nullptr;
    }
    // B pointers: gate rows (4 passes), up rows (4 passes)
    const float* bp[2][4];
#pragma unroll
    for (int p = 0; p < 4; p++) {
        bp[0][p] = gup + ((size_t)e * 2 * FDIM + (n0 + lr + 32 * p)) * HDIM;
        bp[1][p] = bp[0][p] + (size_t)FDIM * HDIM;
    }

    int warp = tid >> 5, lane = tid & 31;
    int gid = lane >> 2, tig = lane & 3;
    int wm = (warp & 1) * 64;        // 2 m-groups of 64
    int wn = (warp >> 1) * 32;       // 4 n-groups of 32

    float acc[2][4][4][4];           // [g][mt][nt][4]
#pragma unroll
    for (int g = 0; g < 2; g++)
#pragma unroll
        for (int mt = 0; mt < 4; mt++)
#pragma unroll
            for (int nt = 0; nt < 4; nt++)
#pragma unroll
                for (int i = 0; i < 4; i++) acc[g][mt][nt][i] = 0.f;

    const float4 f4z = make_float4(0.f, 0.f, 0.f, 0.f);
    float4 pA[4], pB[2][4];
#pragma unroll
    for (int p = 0; p < 4; p++) {
        pA[p] = ap[p] ? *(const float4*)(ap[p] + lc) : f4z;
        pB[0][p] = *(const float4*)(bp[0][p] + lc);
        pB[1][p] = *(const float4*)(bp[1][p] + lc);
    }

    int buf = 0;
    for (int k0 = 0; k0 < HDIM; k0 += BK) {
#pragma unroll
        for (int p = 0; p < 4; p++) {
            st_tf32x4(&As[buf][lr + 32 * p][lc], pA[p]);
            st_tf32x4(&Bs[buf][0][lr + 32 * p][lc], pB[0][p]);
            st_tf32x4(&Bs[buf][1][lr + 32 * p][lc], pB[1][p]);
        }
        __syncthreads();

        int kn = k0 + BK;
        if (kn < HDIM) {
#pragma unroll
            for (int p = 0; p < 4; p++) {
                pA[p] = ap[p] ? *(const float4*)(ap[p] + kn + lc) : f4z;
                pB[0][p] = *(const float4*)(bp[0][p] + kn + lc);
                pB[1][p] = *(const float4*)(bp[1][p] + kn + lc);
            }
        }

#pragma unroll
        for (int kk = 0; kk < BK; kk += 8) {
            uint32_t a[4][4];
#pragma unroll
            for (int mt = 0; mt < 4; mt++) {
                int r = wm + mt * 16 + gid;
                a[mt][0] = As[buf][r][kk + tig];
                a[mt][1] = As[buf][r + 8][kk + tig];
                a[mt][2] = As[buf][r][kk + tig + 4];
                a[mt][3] = As[buf][r + 8][kk + tig + 4];
            }
#pragma unroll
            for (int g = 0; g < 2; g++) {
#pragma unroll
                for (int nt = 0; nt < 4; nt++) {
                    int n = wn + nt * 8 + gid;
                    uint32_t b0 = Bs[buf][g][n][kk + tig];
                    uint32_t b1 = Bs[buf][g][n][kk + tig + 4];
#pragma unroll
                    for (int mt = 0; mt < 4; mt++)
                        mma_tf32(acc[g][mt][nt], a[mt], b0, b1);
                }
            }
        }
        buf ^= 1;
    }

    // epilogue: silu(gate) * up * routing_weight
#pragma unroll
    for (int mt = 0; mt < 4; mt++) {
        int rbase = m0 + wm + mt * 16 + gid;
        float wA = g_perm_weight[rbase];
        float wB = g_perm_weight[rbase + 8];
#pragma unroll
        for (int nt = 0; nt < 4; nt++) {
            int cbase = n0 + wn + nt * 8 + 2 * tig;
#pragma unroll
            for (int i = 0; i < 4; i++) {
                float gv = acc[0][mt][nt][i];
                float uv = acc[1][mt][nt][i];
                float hv = (gv / (1.f + expf(-gv))) * uv;
                int row = rbase + ((i >> 1) ? 8 : 0);
                int col = cbase + (i & 1);
                float wgt = (i >> 1) ? wB : wA;
                g_h[(size_t)row * FDIM + col] = hv * wgt;
            }
        }
    }
}

// ---------------- GEMM2: y = h @ w2^T ----------------------------------------
__global__ void __launch_bounds__(256, 1) gemm2_kernel(
    const float* __restrict__ dw) {
    extern __shared__ uint32_t sm2[];
    uint32_t (*As)[BM][LDN] = (uint32_t (*)[BM][LDN])sm2;
    uint32_t (*Bs)[BN][LDN] = (uint32_t (*)[BN][LDN])(sm2 + 2 * BM * LDN);

    int m0 = blockIdx.x * BM;
    if (m0 >= g_off[EDIM]) return;
    int n0 = blockIdx.y * BN;   // over HDIM
    int e = 0;
    while (m0 >= g_off[e + 1]) e++;

    int tid = threadIdx.x;
    int lr = tid >> 3;
    int lc = (tid & 7) * 4;

    const float* ap[4];
    const float* bp[4];
#pragma unroll
    for (int p = 0; p < 4; p++) {
        ap[p] = g_h + (size_t)(m0 + lr + 32 * p) * FDIM;
        bp[p] = dw + ((size_t)e * HDIM + (n0 + lr + 32 * p)) * FDIM;
    }

    int warp = tid >> 5, lane = tid & 31;
    int gid = lane >> 2, tig = lane & 3;
    int wm = (warp & 1) * 64;
    int wn = (warp >> 1) * 32;

    float acc[4][4][4];
#pragma unroll
    for (int mt = 0; mt < 4; mt++)
#pragma unroll
        for (int nt = 0; nt < 4; nt++)
#pragma unroll
            for (int i = 0; i < 4; i++) acc[mt][nt][i] = 0.f;

    float4 pA[4], pB[4];
#pragma unroll
    for (int p = 0; p < 4; p++) {
        pA[p] = *(const float4*)(ap[p] + lc);
        pB[p] = *(const float4*)(bp[p] + lc);
    }

    int buf = 0;
    for (int k0 = 0; k0 < FDIM; k0 += BK) {
#pragma unroll
        for (int p = 0; p < 4; p++) {
            st_tf32x4(&As[buf][lr + 32 * p][lc], pA[p]);
            st_tf32x4(&Bs[buf][lr + 32 * p][lc], pB[p]);
        }
        __syncthreads();

        int kn = k0 + BK;
        if (kn < FDIM) {
#pragma unroll
            for (int p = 0; p < 4; p++) {
                pA[p] = *(const float4*)(ap[p] + kn + lc);
                pB[p] = *(const float4*)(bp[p] + kn + lc);
            }
        }

#pragma unroll
        for (int kk = 0; kk < BK; kk += 8) {
            uint32_t a[4][4];
#pragma unroll
            for (int mt = 0; mt < 4; mt++) {
                int r = wm + mt * 16 + gid;
                a[mt][0] = As[buf][r][kk + tig];
                a[mt][1] = As[buf][r + 8][kk + tig];
                a[mt][2] = As[buf][r][kk + tig + 4];
                a[mt][3] = As[buf][r + 8][kk + tig + 4];
            }
#pragma unroll
            for (int nt = 0; nt < 4; nt++) {
                int n = wn + nt * 8 + gid;
                uint32_t b0 = Bs[buf][n][kk + tig];
                uint32_t b1 = Bs[buf][n][kk + tig + 4];
#pragma unroll
                for (int mt = 0; mt < 4; mt++)
                    mma_tf32(acc[mt][nt], a[mt], b0, b1);
            }
        }
        buf ^= 1;
    }

#pragma unroll
    for (int mt = 0; mt < 4; mt++) {
        int rbase = m0 + wm + mt * 16 + gid;
#pragma unroll
        for (int nt = 0; nt < 4; nt++) {
            int cbase = n0 + wn + nt * 8 + 2 * tig;
#pragma unroll
            for (int i = 0; i < 4; i++) {
                int row = rbase + ((i >> 1) ? 8 : 0);
                int col = cbase + (i & 1);
                g_y[(size_t)row * HDIM + col] = acc[mt][nt][i];
            }
        }
    }
}

// ---------------- combine: out[t] = y[pos0] + y[pos1] ------------------------
__global__ void combine_kernel(float* __restrict__ out) {
    int i = blockIdx.x * blockDim.x + threadIdx.x;
    if (i >= T_TOK * HDIM) return;
    int t = i >> 10, n = i & (HDIM - 1);
    int p0 = g_token_pos[t * 2 + 0];
    int p1 = g_token_pos[t * 2 + 1];
    out[i] = g_y[(size_t)p0 * HDIM + n] + g_y[(size_t)p1 * HDIM + n];
}

// ---------------- launcher ----------------------------------------------------
extern "C" void kernel_launch(void* const* d_in, const int* in_sizes, int n_in,
                              void* d_out, int out_size) {
    const float* x   = (const float*)d_in[0];   // (2,2048,1024)
    const float* gw  = (const float*)d_in[1];   // (8,1024)
    const float* gup = (const float*)d_in[2];   // (8,8192,1024)
    const float* dw  = (const float*)d_in[3];   // (8,1024,4096)
    float* out = (float*)d_out;                 // out (4194304) ++ logits (32768)
    float* logits = out + (size_t)T_TOK * HDIM;

    const int smem1 = (2 * BM * LDN + 2 * 2 * BN * LDN) * 4;   // 110592 B
    const int smem2 = (2 * BM * LDN + 2 * BN * LDN) * 4;       //  73728 B
    cudaFuncSetAttribute(gemm1_kernel, cudaFuncAttributeMaxDynamicSharedMemorySize, smem1);
    cudaFuncSetAttribute(gemm2_kernel, cudaFuncAttributeMaxDynamicSharedMemorySize, smem2);

    init_kernel<<<(PADROWS + 255) / 256, 256>>>();
    router_kernel<<<T_TOK / 4, 128>>>(x, gw, logits);
    scan_kernel<<<1, 1>>>();
    scatter_kernel<<<(T_TOK + 255) / 256, 256>>>();
    gemm1_kernel<<<dim3(PADROWS / BM, FDIM / BN), 256, smem1>>>(x, gup);
    gemm2_kernel<<<dim3(PADROWS / BM, HDIM / BN), 256, smem2>>>(dw);
    combine_kernel<<<(T_TOK * HDIM) / 256, 256>>>(out);
    (void)in_sizes; (void)n_in; (void)out_size;
}

// round 5
// speedup vs baseline: 2.4843x; 1.4709x over previous
#include <cuda_runtime.h>
#include <cuda_fp16.h>
#include <cstdint>

// Problem constants (fixed shapes)
#define T_TOK 4096
#define HDIM  1024
#define FDIM  4096
#define EDIM  8
#define BM 128
#define BN 128
#define BK 32           // K halves per slab (2 x k16 mma steps)
#define LDN 20          // smem row stride in 32-bit words (16 data + 4 pad)
#define PADROWS 9216    // 8192 + 8*128 worst-case segment padding

// ---------------- scratch (static device globals; no allocation) ----------
__device__ __align__(16) __half g_h[(size_t)PADROWS * FDIM];  // fp16 intermediate
__device__ __align__(16) float g_y[(size_t)PADROWS * HDIM];
__device__ int   g_perm_token[PADROWS];
__device__ float g_perm_weight[PADROWS];
__device__ int   g_token_pos[T_TOK * 2];
__device__ int   g_te[T_TOK * 2];
__device__ float g_tw[T_TOK * 2];
__device__ int   g_counts[EDIM];
__device__ int   g_cursor[EDIM];
__device__ int   g_off[EDIM + 1];

// ---------------- helpers ---------------------------------------------------
__device__ __forceinline__ uint32_t h2u(__half2 h) {
    return *(uint32_t*)&h;
}

__device__ __forceinline__ uint2 cvt4h(float4 v) {
    uint2 u;
    u.x = h2u(__floats2half2_rn(v.x, v.y));
    u.y = h2u(__floats2half2_rn(v.z, v.w));
    return u;
}

__device__ __forceinline__ void mma_f16(float c[4], const uint32_t a[4],
                                        uint32_t b0, uint32_t b1) {
    asm volatile(
        "mma.sync.aligned.m16n8k16.row.col.f32.f16.f16.f32 "
        "{%0,%1,%2,%3}, {%4,%5,%6,%7}, {%8,%9}, {%0,%1,%2,%3};\n"
        : "+f"(c[0]), "+f"(c[1]), "+f"(c[2]), "+f"(c[3])
        : "r"(a[0]), "r"(a[1]), "r"(a[2]), "r"(a[3]), "r"(b0), "r"(b1));
}

// ---------------- init ------------------------------------------------------
__global__ void init_kernel() {
    int i = blockIdx.x * blockDim.x + threadIdx.x;
    if (i < PADROWS) {
        g_perm_token[i] = -1;
        g_perm_weight[i] = 0.f;
    }
    if (i < EDIM) g_counts[i] = 0;
}

// ---------------- router: logits + softmax top2 -----------------------------
__global__ void __launch_bounds__(128) router_kernel(
    const float* __restrict__ x, const float* __restrict__ gw,
    float* __restrict__ logits_out) {
    __shared__ float sgw[EDIM * HDIM];
    int tid = threadIdx.x;
    for (int i = tid; i < EDIM * HDIM; i += 128) sgw[i] = gw[i];
    __syncthreads();

    int warp = tid >> 5, lane = tid & 31;
    int t = blockIdx.x * 4 + warp;
    const float* xr = x + (size_t)t * HDIM;

    float acc[EDIM];
#pragma unroll
    for (int e = 0; e < EDIM; e++) acc[e] = 0.f;
    for (int j = lane; j < HDIM; j += 32) {
        float xv = xr[j];
#pragma unroll
        for (int e = 0; e < EDIM; e++) acc[e] = fmaf(xv, sgw[e * HDIM + j], acc[e]);
    }
#pragma unroll
    for (int e = 0; e < EDIM; e++)
#pragma unroll
        for (int o = 16; o > 0; o >>= 1)
            acc[e] += __shfl_xor_sync(0xffffffffu, acc[e], o);

    if (lane == 0) {
#pragma unroll
        for (int e = 0; e < EDIM; e++) logits_out[t * EDIM + e] = acc[e];
        int e0 = 0; float l0 = acc[0];
#pragma unroll
        for (int e = 1; e < EDIM; e++) if (acc[e] > l0) { l0 = acc[e]; e0 = e; }
        int e1 = -1; float l1 = -3.4e38f;
#pragma unroll
        for (int e = 0; e < EDIM; e++)
            if (e != e0 && acc[e] > l1) { l1 = acc[e]; e1 = e; }
        float r = expf(l1 - l0);
        float w0 = 1.f / (1.f + r);
        float w1 = r / (1.f + r);
        g_te[t * 2 + 0] = e0; g_tw[t * 2 + 0] = w0;
        g_te[t * 2 + 1] = e1; g_tw[t * 2 + 1] = w1;
        atomicAdd(&g_counts[e0], 1);
        atomicAdd(&g_counts[e1], 1);
    }
}

// ---------------- scan ------------------------------------------------------
__global__ void scan_kernel() {
    int off = 0;
    for (int e = 0; e < EDIM; e++) {
        g_off[e] = off;
        g_cursor[e] = off;
        off += ((g_counts[e] + BM - 1) / BM) * BM;
    }
    g_off[EDIM] = off;
}

// ---------------- scatter ---------------------------------------------------
__global__ void scatter_kernel() {
    int t = blockIdx.x * blockDim.x + threadIdx.x;
    if (t >= T_TOK) return;
#pragma unroll
    for (int k = 0; k < 2; k++) {
        int e = g_te[t * 2 + k];
        int pos = atomicAdd(&g_cursor[e], 1);
        g_perm_token[pos] = t;
        g_perm_weight[pos] = g_tw[t * 2 + k];
        g_token_pos[t * 2 + k] = pos;
    }
}

// ---------------- GEMM1: h = silu(x@w1^T) * (x@w3^T) * route_w ---------------
// 256 threads / 8 warps; fp16 m16n8k16; double-buffered; warp tile 64x(2g x 32).
__global__ void __launch_bounds__(256, 1) gemm1_kernel(
    const float* __restrict__ x, const float* __restrict__ gup) {
    extern __shared__ uint32_t sm1[];
    uint32_t (*As)[BM][LDN] = (uint32_t (*)[BM][LDN])sm1;
    uint32_t (*Bs)[2][BN][LDN] = (uint32_t (*)[2][BN][LDN])(sm1 + 2 * BM * LDN);

    int m0 = blockIdx.x * BM;
    if (m0 >= g_off[EDIM]) return;
    int n0 = blockIdx.y * BN;
    int e = 0;
    while (m0 >= g_off[e + 1]) e++;

    int tid = threadIdx.x;
    int lr = tid >> 3;            // 0..31 (row within pass)
    int lcf = (tid & 7) * 4;      // float col (loads float4 = 4 halves out)
    int lcw = (tid & 7) * 2;      // smem word col for the 4 halves

    const float* ap[4];
#pragma unroll
    for (int p = 0; p < 4; p++) {
        int tok = g_perm_token[m0 + lr + 32 * p];
        ap[p] = (tok >= 0) ? (x + (size_t)tok * HDIM) : nullptr;
    }
    const float* bp[2][4];
#pragma unroll
    for (int p = 0; p < 4; p++) {
        bp[0][p] = gup + ((size_t)e * 2 * FDIM + (n0 + lr + 32 * p)) * HDIM;
        bp[1][p] = bp[0][p] + (size_t)FDIM * HDIM;
    }

    int warp = tid >> 5, lane = tid & 31;
    int gid = lane >> 2, tig = lane & 3;
    int wm = (warp & 1) * 64;        // 2 m-groups of 64
    int wn = (warp >> 1) * 32;       // 4 n-groups of 32

    float acc[2][4][4][4];
#pragma unroll
    for (int g = 0; g < 2; g++)
#pragma unroll
        for (int mt = 0; mt < 4; mt++)
#pragma unroll
            for (int nt = 0; nt < 4; nt++)
#pragma unroll
                for (int i = 0; i < 4; i++) acc[g][mt][nt][i] = 0.f;

    const float4 f4z = make_float4(0.f, 0.f, 0.f, 0.f);
    float4 pA[4], pB[2][4];
#pragma unroll
    for (int p = 0; p < 4; p++) {
        pA[p] = ap[p] ? *(const float4*)(ap[p] + lcf) : f4z;
        pB[0][p] = *(const float4*)(bp[0][p] + lcf);
        pB[1][p] = *(const float4*)(bp[1][p] + lcf);
    }

    int buf = 0;
    for (int k0 = 0; k0 < HDIM; k0 += BK) {
#pragma unroll
        for (int p = 0; p < 4; p++) {
            *(uint2*)&As[buf][lr + 32 * p][lcw] = cvt4h(pA[p]);
            *(uint2*)&Bs[buf][0][lr + 32 * p][lcw] = cvt4h(pB[0][p]);
            *(uint2*)&Bs[buf][1][lr + 32 * p][lcw] = cvt4h(pB[1][p]);
        }
        __syncthreads();

        int kn = k0 + BK;
        if (kn < HDIM) {
#pragma unroll
            for (int p = 0; p < 4; p++) {
                pA[p] = ap[p] ? *(const float4*)(ap[p] + kn + lcf) : f4z;
                pB[0][p] = *(const float4*)(bp[0][p] + kn + lcf);
                pB[1][p] = *(const float4*)(bp[1][p] + kn + lcf);
            }
        }

#pragma unroll
        for (int kk = 0; kk < 16; kk += 8) {   // 2 k16 steps (word offsets)
            uint32_t a[4][4];
#pragma unroll
            for (int mt = 0; mt < 4; mt++) {
                int r = wm + mt * 16 + gid;
                a[mt][0] = As[buf][r][kk + tig];
                a[mt][1] = As[buf][r + 8][kk + tig];
                a[mt][2] = As[buf][r][kk + tig + 4];
                a[mt][3] = As[buf][r + 8][kk + tig + 4];
            }
#pragma unroll
            for (int g = 0; g < 2; g++) {
#pragma unroll
                for (int nt = 0; nt < 4; nt++) {
                    int n = wn + nt * 8 + gid;
                    uint32_t b0 = Bs[buf][g][n][kk + tig];
                    uint32_t b1 = Bs[buf][g][n][kk + tig + 4];
#pragma unroll
                    for (int mt = 0; mt < 4; mt++)
                        mma_f16(acc[g][mt][nt], a[mt], b0, b1);
                }
            }
        }
        buf ^= 1;
    }

    // epilogue: silu(gate) * up * routing_weight -> fp16 g_h (half2 stores)
#pragma unroll
    for (int mt = 0; mt < 4; mt++) {
        int rbase = m0 + wm + mt * 16 + gid;
        float wA = g_perm_weight[rbase];
        float wB = g_perm_weight[rbase + 8];
#pragma unroll
        for (int nt = 0; nt < 4; nt++) {
            int cbase = n0 + wn + nt * 8 + 2 * tig;
            float h0 = (acc[0][mt][nt][0] / (1.f + expf(-acc[0][mt][nt][0]))) *
                       acc[1][mt][nt][0] * wA;
            float h1 = (acc[0][mt][nt][1] / (1.f + expf(-acc[0][mt][nt][1]))) *
                       acc[1][mt][nt][1] * wA;
            float h2 = (acc[0][mt][nt][2] / (1.f + expf(-acc[0][mt][nt][2]))) *
                       acc[1][mt][nt][2] * wB;
            float h3 = (acc[0][mt][nt][3] / (1.f + expf(-acc[0][mt][nt][3]))) *
                       acc[1][mt][nt][3] * wB;
            *(uint32_t*)&g_h[(size_t)rbase * FDIM + cbase] =
                h2u(__floats2half2_rn(h0, h1));
            *(uint32_t*)&g_h[(size_t)(rbase + 8) * FDIM + cbase] =
                h2u(__floats2half2_rn(h2, h3));
        }
    }
}

// ---------------- GEMM2: y = h @ w2^T ----------------------------------------
__global__ void __launch_bounds__(256, 1) gemm2_kernel(
    const float* __restrict__ dw) {
    extern __shared__ uint32_t sm2[];
    uint32_t (*As)[BM][LDN] = (uint32_t (*)[BM][LDN])sm2;
    uint32_t (*Bs)[BN][LDN] = (uint32_t (*)[BN][LDN])(sm2 + 2 * BM * LDN);

    int m0 = blockIdx.x * BM;
    if (m0 >= g_off[EDIM]) return;
    int n0 = blockIdx.y * BN;   // over HDIM
    int e = 0;
    while (m0 >= g_off[e + 1]) e++;

    int tid = threadIdx.x;
    int lr = tid >> 3;
    int lcf = (tid & 7) * 4;      // element col (4 halves / 4 floats)
    int lcw = (tid & 7) * 2;

    const __half* ap[4];
    const float* bp[4];
#pragma unroll
    for (int p = 0; p < 4; p++) {
        ap[p] = g_h + (size_t)(m0 + lr + 32 * p) * FDIM;
        bp[p] = dw + ((size_t)e * HDIM + (n0 + lr + 32 * p)) * FDIM;
    }

    int warp = tid >> 5, lane = tid & 31;
    int gid = lane >> 2, tig = lane & 3;
    int wm = (warp & 1) * 64;
    int wn = (warp >> 1) * 32;

    float acc[4][4][4];
#pragma unroll
    for (int mt = 0; mt < 4; mt++)
#pragma unroll
        for (int nt = 0; nt < 4; nt++)
#pragma unroll
            for (int i = 0; i < 4; i++) acc[mt][nt][i] = 0.f;

    uint2 pA[4];
    float4 pB[4];
#pragma unroll
    for (int p = 0; p < 4; p++) {
        pA[p] = *(const uint2*)(ap[p] + lcf);
        pB[p] = *(const float4*)(bp[p] + lcf);
    }

    int buf = 0;
    for (int k0 = 0; k0 < FDIM; k0 += BK) {
#pragma unroll
        for (int p = 0; p < 4; p++) {
            *(uint2*)&As[buf][lr + 32 * p][lcw] = pA[p];
            *(uint2*)&Bs[buf][lr + 32 * p][lcw] = cvt4h(pB[p]);
        }
        __syncthreads();

        int kn = k0 + BK;
        if (kn < FDIM) {
#pragma unroll
            for (int p = 0; p < 4; p++) {
                pA[p] = *(const uint2*)(ap[p] + kn + lcf);
                pB[p] = *(const float4*)(bp[p] + kn + lcf);
            }
        }

#pragma unroll
        for (int kk = 0; kk < 16; kk += 8) {
            uint32_t a[4][4];
#pragma unroll
            for (int mt = 0; mt < 4; mt++) {
                int r = wm + mt * 16 + gid;
                a[mt][0] = As[buf][r][kk + tig];
                a[mt][1] = As[buf][r + 8][kk + tig];
                a[mt][2] = As[buf][r][kk + tig + 4];
                a[mt][3] = As[buf][r + 8][kk + tig + 4];
            }
#pragma unroll
            for (int nt = 0; nt < 4; nt++) {
                int n = wn + nt * 8 + gid;
                uint32_t b0 = Bs[buf][n][kk + tig];
                uint32_t b1 = Bs[buf][n][kk + tig + 4];
#pragma unroll
                for (int mt = 0; mt < 4; mt++)
                    mma_f16(acc[mt][nt], a[mt], b0, b1);
            }
        }
        buf ^= 1;
    }

#pragma unroll
    for (int mt = 0; mt < 4; mt++) {
        int rbase = m0 + wm + mt * 16 + gid;
#pragma unroll
        for (int nt = 0; nt < 4; nt++) {
            int cbase = n0 + wn + nt * 8 + 2 * tig;
            *(float2*)&g_y[(size_t)rbase * HDIM + cbase] =
                make_float2(acc[mt][nt][0], acc[mt][nt][1]);
            *(float2*)&g_y[(size_t)(rbase + 8) * HDIM + cbase] =
                make_float2(acc[mt][nt][2], acc[mt][nt][3]);
        }
    }
}

// ---------------- combine: out[t] = y[pos0] + y[pos1] ------------------------
__global__ void combine_kernel(float* __restrict__ out) {
    int i = blockIdx.x * blockDim.x + threadIdx.x;
    if (i >= T_TOK * HDIM) return;
    int t = i >> 10, n = i & (HDIM - 1);
    int p0 = g_token_pos[t * 2 + 0];
    int p1 = g_token_pos[t * 2 + 1];
    out[i] = g_y[(size_t)p0 * HDIM + n] + g_y[(size_t)p1 * HDIM + n];
}

// ---------------- launcher ----------------------------------------------------
extern "C" void kernel_launch(void* const* d_in, const int* in_sizes, int n_in,
                              void* d_out, int out_size) {
    const float* x   = (const float*)d_in[0];   // (2,2048,1024)
    const float* gw  = (const float*)d_in[1];   // (8,1024)
    const float* gup = (const float*)d_in[2];   // (8,8192,1024)
    const float* dw  = (const float*)d_in[3];   // (8,1024,4096)
    float* out = (float*)d_out;                 // out (4194304) ++ logits (32768)
    float* logits = out + (size_t)T_TOK * HDIM;

    const int smem1 = (2 * BM * LDN + 2 * 2 * BN * LDN) * 4;   // 61440 B
    const int smem2 = (2 * BM * LDN + 2 * BN * LDN) * 4;       // 40960 B
    cudaFuncSetAttribute(gemm1_kernel, cudaFuncAttributeMaxDynamicSharedMemorySize, smem1);
    cudaFuncSetAttribute(gemm2_kernel, cudaFuncAttributeMaxDynamicSharedMemorySize, smem2);

    init_kernel<<<(PADROWS + 255) / 256, 256>>>();
    router_kernel<<<T_TOK / 4, 128>>>(x, gw, logits);
    scan_kernel<<<1, 1>>>();
    scatter_kernel<<<(T_TOK + 255) / 256, 256>>>();
    gemm1_kernel<<<dim3(PADROWS / BM, FDIM / BN), 256, smem1>>>(x, gup);
    gemm2_kernel<<<dim3(PADROWS / BM, HDIM / BN), 256, smem2>>>(dw);
    combine_kernel<<<(T_TOK * HDIM) / 256, 256>>>(out);
    (void)in_sizes; (void)n_in; (void)out_size;
}

// round 6
// speedup vs baseline: 2.5813x; 1.0390x over previous
#include <cuda_runtime.h>
#include <cuda_fp16.h>
#include <cstdint>

// Problem constants (fixed shapes)
#define T_TOK 4096
#define HDIM  1024
#define FDIM  4096
#define EDIM  8
#define BM 128
#define BN 128
#define BKH 64          // K halves per slab (4 x k16 mma steps)
#define LDNW 36         // smem row stride in 32-bit words (32 data + 4 pad) = 144B
#define ROWB 144        // row bytes
#define PADROWS 9216    // 8192 + 8*128 worst-case segment padding

// ---------------- scratch (static device globals; no allocation) ----------
__device__ __align__(16) __half g_wgup[(size_t)EDIM * 2 * FDIM * HDIM]; // 134MB
__device__ __align__(16) __half g_wdw[(size_t)EDIM * HDIM * FDIM];      // 67MB
__device__ __align__(16) __half g_x16[(size_t)T_TOK * HDIM];            // 8.4MB
__device__ __align__(16) __half g_h[(size_t)PADROWS * FDIM];            // 75MB
__device__ __align__(16) float  g_y[(size_t)PADROWS * HDIM];            // 38MB
__device__ int   g_perm_token[PADROWS];
__device__ float g_perm_weight[PADROWS];
__device__ int   g_token_pos[T_TOK * 2];
__device__ int   g_te[T_TOK * 2];
__device__ float g_tw[T_TOK * 2];
__device__ int   g_counts[EDIM];
__device__ int   g_cursor[EDIM];
__device__ int   g_off[EDIM + 1];

// ---------------- helpers ---------------------------------------------------
__device__ __forceinline__ uint32_t h2u(__half2 h) { return *(uint32_t*)&h; }

__device__ __forceinline__ uint32_t smem_u32(const void* p) {
    uint32_t a;
    asm("{ .reg .u64 t; cvta.to.shared.u64 t, %1; cvt.u32.u64 %0, t; }"
        : "=r"(a) : "l"(p));
    return a;
}

__device__ __forceinline__ void ldsm4(uint32_t& r0, uint32_t& r1,
                                      uint32_t& r2, uint32_t& r3, uint32_t addr) {
    asm volatile("ldmatrix.sync.aligned.m8n8.x4.shared.b16 {%0,%1,%2,%3}, [%4];"
                 : "=r"(r0), "=r"(r1), "=r"(r2), "=r"(r3) : "r"(addr));
}

__device__ __forceinline__ void mma_f16(float c[4], const uint32_t a[4],
                                        uint32_t b0, uint32_t b1) {
    asm volatile(
        "mma.sync.aligned.m16n8k16.row.col.f32.f16.f16.f32 "
        "{%0,%1,%2,%3}, {%4,%5,%6,%7}, {%8,%9}, {%0,%1,%2,%3};\n"
        : "+f"(c[0]), "+f"(c[1]), "+f"(c[2]), "+f"(c[3])
        : "r"(a[0]), "r"(a[1]), "r"(a[2]), "r"(a[3]), "r"(b0), "r"(b1));
}

// ---------------- fp32 -> fp16 conversion (one pass per tensor) ---------------
__global__ void cvt_kernel(const float* __restrict__ s, __half* __restrict__ d,
                           int n8) {
    int i = blockIdx.x * blockDim.x + threadIdx.x;
    if (i >= n8) return;
    const float4* s4 = (const float4*)s + (size_t)i * 2;
    float4 v0 = s4[0], v1 = s4[1];
    uint4 o;
    o.x = h2u(__floats2half2_rn(v0.x, v0.y));
    o.y = h2u(__floats2half2_rn(v0.z, v0.w));
    o.z = h2u(__floats2half2_rn(v1.x, v1.y));
    o.w = h2u(__floats2half2_rn(v1.z, v1.w));
    ((uint4*)d)[i] = o;
}

// ---------------- init ------------------------------------------------------
__global__ void init_kernel() {
    int i = blockIdx.x * blockDim.x + threadIdx.x;
    if (i < PADROWS) {
        g_perm_token[i] = -1;
        g_perm_weight[i] = 0.f;
    }
    if (i < EDIM) g_counts[i] = 0;
}

// ---------------- router: logits + softmax top2 -----------------------------
__global__ void __launch_bounds__(128) router_kernel(
    const float* __restrict__ x, const float* __restrict__ gw,
    float* __restrict__ logits_out) {
    __shared__ float sgw[EDIM * HDIM];
    int tid = threadIdx.x;
    for (int i = tid; i < EDIM * HDIM; i += 128) sgw[i] = gw[i];
    __syncthreads();

    int warp = tid >> 5, lane = tid & 31;
    int t = blockIdx.x * 4 + warp;
    const float* xr = x + (size_t)t * HDIM;

    float acc[EDIM];
#pragma unroll
    for (int e = 0; e < EDIM; e++) acc[e] = 0.f;
    for (int j = lane; j < HDIM; j += 32) {
        float xv = xr[j];
#pragma unroll
        for (int e = 0; e < EDIM; e++) acc[e] = fmaf(xv, sgw[e * HDIM + j], acc[e]);
    }
#pragma unroll
    for (int e = 0; e < EDIM; e++)
#pragma unroll
        for (int o = 16; o > 0; o >>= 1)
            acc[e] += __shfl_xor_sync(0xffffffffu, acc[e], o);

    if (lane == 0) {
#pragma unroll
        for (int e = 0; e < EDIM; e++) logits_out[t * EDIM + e] = acc[e];
        int e0 = 0; float l0 = acc[0];
#pragma unroll
        for (int e = 1; e < EDIM; e++) if (acc[e] > l0) { l0 = acc[e]; e0 = e; }
        int e1 = -1; float l1 = -3.4e38f;
#pragma unroll
        for (int e = 0; e < EDIM; e++)
            if (e != e0 && acc[e] > l1) { l1 = acc[e]; e1 = e; }
        float r = expf(l1 - l0);
        float w0 = 1.f / (1.f + r);
        float w1 = r / (1.f + r);
        g_te[t * 2 + 0] = e0; g_tw[t * 2 + 0] = w0;
        g_te[t * 2 + 1] = e1; g_tw[t * 2 + 1] = w1;
        atomicAdd(&g_counts[e0], 1);
        atomicAdd(&g_counts[e1], 1);
    }
}

// ---------------- scan ------------------------------------------------------
__global__ void scan_kernel() {
    int off = 0;
    for (int e = 0; e < EDIM; e++) {
        g_off[e] = off;
        g_cursor[e] = off;
        off += ((g_counts[e] + BM - 1) / BM) * BM;
    }
    g_off[EDIM] = off;
}

// ---------------- scatter ---------------------------------------------------
__global__ void scatter_kernel() {
    int t = blockIdx.x * blockDim.x + threadIdx.x;
    if (t >= T_TOK) return;
#pragma unroll
    for (int k = 0; k < 2; k++) {
        int e = g_te[t * 2 + k];
        int pos = atomicAdd(&g_cursor[e], 1);
        g_perm_token[pos] = t;
        g_perm_weight[pos] = g_tw[t * 2 + k];
        g_token_pos[t * 2 + k] = pos;
    }
}

// ---------------- GEMM1: h = silu(x@w1^T) * (x@w3^T) * route_w ---------------
// 256 threads / 8 warps; fp16 inputs; ldmatrix frags; BK=64 halves; dbl-buffered.
__global__ void __launch_bounds__(256, 1) gemm1_kernel() {
    extern __shared__ char sm1[];
    // As[2][128][ROWB] then Bs[2][2][128][ROWB] bytes
    const uint32_t ABUF = 128 * ROWB;            // 18432
    const uint32_t GOFF = 128 * ROWB;            // within one B buffer: gate|up
    const uint32_t BBUF = 2 * 128 * ROWB;        // 36864
    char* Asm = sm1;
    char* Bsm = sm1 + 2 * ABUF;
    uint32_t asB = smem_u32(Asm);
    uint32_t bsB = smem_u32(Bsm);

    int m0 = blockIdx.x * BM;
    if (m0 >= g_off[EDIM]) return;
    int n0 = blockIdx.y * BN;
    int e = 0;
    while (m0 >= g_off[e + 1]) e++;

    int tid = threadIdx.x;
    int r = tid >> 1;             // staging row 0..127
    int seg = tid & 1;            // half-row segment (32 halves)

    int tok = g_perm_token[m0 + r];
    const __half* arow = (tok >= 0)
        ? g_x16 + (size_t)tok * HDIM + seg * 32 : nullptr;
    const __half* bgrow = g_wgup + ((size_t)e * 2 * FDIM + (n0 + r)) * HDIM + seg * 32;
    const __half* burow = bgrow + (size_t)FDIM * HDIM;
    uint32_t stoff = (uint32_t)(r * ROWB + seg * 64);   // byte offset in tile

    int warp = tid >> 5, lane = tid & 31;
    int gid = lane >> 2, tig = lane & 3;
    int wm = (warp & 1) * 64;
    int wn = (warp >> 1) * 32;

    // ldmatrix lane addressing (within a tile)
    uint32_t aLrow = (uint32_t)(wm + (lane & 15));
    uint32_t aLcol = (uint32_t)((lane >> 4) * 16);       // bytes (8 halves)
    uint32_t bLrow = (uint32_t)(wn + (lane & 7) + ((lane >> 4) & 1) * 8);
    uint32_t bLcol = (uint32_t)(((lane >> 3) & 1) * 16); // bytes

    float acc[2][4][4][4];
#pragma unroll
    for (int g = 0; g < 2; g++)
#pragma unroll
        for (int mt = 0; mt < 4; mt++)
#pragma unroll
            for (int nt = 0; nt < 4; nt++)
#pragma unroll
                for (int i = 0; i < 4; i++) acc[g][mt][nt][i] = 0.f;

    const uint4 z4 = make_uint4(0, 0, 0, 0);
    uint4 pA[4], pG[4], pU[4];
#pragma unroll
    for (int i = 0; i < 4; i++) {
        pA[i] = arow ? *(const uint4*)(arow + i * 8) : z4;
        pG[i] = *(const uint4*)(bgrow + i * 8);
        pU[i] = *(const uint4*)(burow + i * 8);
    }

    for (int s = 0; s < HDIM / BKH; s++) {
        int buf = s & 1;
        char* At = Asm + buf * ABUF;
        char* Bt = Bsm + buf * BBUF;
#pragma unroll
        for (int i = 0; i < 4; i++) {
            *(uint4*)(At + stoff + i * 16) = pA[i];
            *(uint4*)(Bt + stoff + i * 16) = pG[i];
            *(uint4*)(Bt + GOFF + stoff + i * 16) = pU[i];
        }
        __syncthreads();

        if (s + 1 < HDIM / BKH) {
            int k = (s + 1) * BKH;
#pragma unroll
            for (int i = 0; i < 4; i++) {
                pA[i] = arow ? *(const uint4*)(arow + k + i * 8) : z4;
                pG[i] = *(const uint4*)(bgrow + k + i * 8);
                pU[i] = *(const uint4*)(burow + k + i * 8);
            }
        }

        uint32_t aTile = asB + buf * ABUF;
        uint32_t bTile = bsB + buf * BBUF;
#pragma unroll
        for (int ks = 0; ks < 4; ks++) {
            uint32_t kbA = ks * 32 + aLcol;   // bytes into row
            uint32_t kbB = ks * 32 + bLcol;
            uint32_t a[4][4];
#pragma unroll
            for (int mt = 0; mt < 4; mt++)
                ldsm4(a[mt][0], a[mt][1], a[mt][2], a[mt][3],
                      aTile + (aLrow + mt * 16) * ROWB + kbA);
#pragma unroll
            for (int g = 0; g < 2; g++) {
#pragma unroll
                for (int np = 0; np < 2; np++) {
                    uint32_t b0, b1, b2, b3;
                    ldsm4(b0, b1, b2, b3,
                          bTile + g * GOFF + (bLrow + np * 16) * ROWB + kbB);
#pragma unroll
                    for (int mt = 0; mt < 4; mt++) {
                        mma_f16(acc[g][mt][np * 2 + 0], a[mt], b0, b1);
                        mma_f16(acc[g][mt][np * 2 + 1], a[mt], b2, b3);
                    }
                }
            }
        }
        __syncthreads();
    }

    // epilogue: silu(gate) * up * routing_weight -> fp16 g_h
#pragma unroll
    for (int mt = 0; mt < 4; mt++) {
        int rbase = m0 + wm + mt * 16 + gid;
        float wA = g_perm_weight[rbase];
        float wB = g_perm_weight[rbase + 8];
#pragma unroll
        for (int nt = 0; nt < 4; nt++) {
            int cbase = n0 + wn + nt * 8 + 2 * tig;
            float h0 = (acc[0][mt][nt][0] / (1.f + expf(-acc[0][mt][nt][0]))) *
                       acc[1][mt][nt][0] * wA;
            float h1 = (acc[0][mt][nt][1] / (1.f + expf(-acc[0][mt][nt][1]))) *
                       acc[1][mt][nt][1] * wA;
            float h2 = (acc[0][mt][nt][2] / (1.f + expf(-acc[0][mt][nt][2]))) *
                       acc[1][mt][nt][2] * wB;
            float h3 = (acc[0][mt][nt][3] / (1.f + expf(-acc[0][mt][nt][3]))) *
                       acc[1][mt][nt][3] * wB;
            *(uint32_t*)&g_h[(size_t)rbase * FDIM + cbase] =
                h2u(__floats2half2_rn(h0, h1));
            *(uint32_t*)&g_h[(size_t)(rbase + 8) * FDIM + cbase] =
                h2u(__floats2half2_rn(h2, h3));
        }
    }
}

// ---------------- GEMM2: y = h @ w2^T ----------------------------------------
__global__ void __launch_bounds__(256, 1) gemm2_kernel() {
    extern __shared__ char sm2[];
    const uint32_t ABUF = 128 * ROWB;
    const uint32_t BBUF = 128 * ROWB;
    char* Asm = sm2;
    char* Bsm = sm2 + 2 * ABUF;
    uint32_t asB = smem_u32(Asm);
    uint32_t bsB = smem_u32(Bsm);

    int m0 = blockIdx.x * BM;
    if (m0 >= g_off[EDIM]) return;
    int n0 = blockIdx.y * BN;   // over HDIM
    int e = 0;
    while (m0 >= g_off[e + 1]) e++;

    int tid = threadIdx.x;
    int r = tid >> 1;
    int seg = tid & 1;

    const __half* arow = g_h + (size_t)(m0 + r) * FDIM + seg * 32;
    const __half* brow = g_wdw + ((size_t)e * HDIM + (n0 + r)) * FDIM + seg * 32;
    uint32_t stoff = (uint32_t)(r * ROWB + seg * 64);

    int warp = tid >> 5, lane = tid & 31;
    int gid = lane >> 2, tig = lane & 3;
    int wm = (warp & 1) * 64;
    int wn = (warp >> 1) * 32;

    uint32_t aLrow = (uint32_t)(wm + (lane & 15));
    uint32_t aLcol = (uint32_t)((lane >> 4) * 16);
    uint32_t bLrow = (uint32_t)(wn + (lane & 7) + ((lane >> 4) & 1) * 8);
    uint32_t bLcol = (uint32_t)(((lane >> 3) & 1) * 16);

    float acc[4][4][4];
#pragma unroll
    for (int mt = 0; mt < 4; mt++)
#pragma unroll
        for (int nt = 0; nt < 4; nt++)
#pragma unroll
            for (int i = 0; i < 4; i++) acc[mt][nt][i] = 0.f;

    uint4 pA[4], pB[4];
#pragma unroll
    for (int i = 0; i < 4; i++) {
        pA[i] = *(const uint4*)(arow + i * 8);
        pB[i] = *(const uint4*)(brow + i * 8);
    }

    for (int s = 0; s < FDIM / BKH; s++) {
        int buf = s & 1;
        char* At = Asm + buf * ABUF;
        char* Bt = Bsm + buf * BBUF;
#pragma unroll
        for (int i = 0; i < 4; i++) {
            *(uint4*)(At + stoff + i * 16) = pA[i];
            *(uint4*)(Bt + stoff + i * 16) = pB[i];
        }
        __syncthreads();

        if (s + 1 < FDIM / BKH) {
            int k = (s + 1) * BKH;
#pragma unroll
            for (int i = 0; i < 4; i++) {
                pA[i] = *(const uint4*)(arow + k + i * 8);
                pB[i] = *(const uint4*)(brow + k + i * 8);
            }
        }

        uint32_t aTile = asB + buf * ABUF;
        uint32_t bTile = bsB + buf * BBUF;
#pragma unroll
        for (int ks = 0; ks < 4; ks++) {
            uint32_t kbA = ks * 32 + aLcol;
            uint32_t kbB = ks * 32 + bLcol;
            uint32_t a[4][4];
#pragma unroll
            for (int mt = 0; mt < 4; mt++)
                ldsm4(a[mt][0], a[mt][1], a[mt][2], a[mt][3],
                      aTile + (aLrow + mt * 16) * ROWB + kbA);
#pragma unroll
            for (int np = 0; np < 2; np++) {
                uint32_t b0, b1, b2, b3;
                ldsm4(b0, b1, b2, b3,
                      bTile + (bLrow + np * 16) * ROWB + kbB);
#pragma unroll
                for (int mt = 0; mt < 4; mt++) {
                    mma_f16(acc[mt][np * 2 + 0], a[mt], b0, b1);
                    mma_f16(acc[mt][np * 2 + 1], a[mt], b2, b3);
                }
            }
        }
        __syncthreads();
    }

#pragma unroll
    for (int mt = 0; mt < 4; mt++) {
        int rbase = m0 + wm + mt * 16 + gid;
#pragma unroll
        for (int nt = 0; nt < 4; nt++) {
            int cbase = n0 + wn + nt * 8 + 2 * tig;
            *(float2*)&g_y[(size_t)rbase * HDIM + cbase] =
                make_float2(acc[mt][nt][0], acc[mt][nt][1]);
            *(float2*)&g_y[(size_t)(rbase + 8) * HDIM + cbase] =
                make_float2(acc[mt][nt][2], acc[mt][nt][3]);
        }
    }
}

// ---------------- combine: out[t] = y[pos0] + y[pos1] ------------------------
__global__ void combine_kernel(float* __restrict__ out) {
    int i = blockIdx.x * blockDim.x + threadIdx.x;
    if (i >= T_TOK * HDIM) return;
    int t = i >> 10, n = i & (HDIM - 1);
    int p0 = g_token_pos[t * 2 + 0];
    int p1 = g_token_pos[t * 2 + 1];
    out[i] = g_y[(size_t)p0 * HDIM + n] + g_y[(size_t)p1 * HDIM + n];
}

// ---------------- launcher ----------------------------------------------------
extern "C" void kernel_launch(void* const* d_in, const int* in_sizes, int n_in,
                              void* d_out, int out_size) {
    const float* x   = (const float*)d_in[0];   // (2,2048,1024)
    const float* gw  = (const float*)d_in[1];   // (8,1024)
    const float* gup = (const float*)d_in[2];   // (8,8192,1024)
    const float* dw  = (const float*)d_in[3];   // (8,1024,4096)
    float* out = (float*)d_out;                 // out (4194304) ++ logits (32768)
    float* logits = out + (size_t)T_TOK * HDIM;

    const int smem1 = 2 * 128 * ROWB + 2 * 2 * 128 * ROWB;  // 110592 B
    const int smem2 = 2 * 128 * ROWB + 2 * 128 * ROWB;      //  73728 B
    cudaFuncSetAttribute(gemm1_kernel, cudaFuncAttributeMaxDynamicSharedMemorySize, smem1);
    cudaFuncSetAttribute(gemm2_kernel, cudaFuncAttributeMaxDynamicSharedMemorySize, smem2);

    __half* d_wgup; cudaGetSymbolAddress((void**)&d_wgup, g_wgup);
    __half* d_wdw;  cudaGetSymbolAddress((void**)&d_wdw,  g_wdw);
    __half* d_x16;  cudaGetSymbolAddress((void**)&d_x16,  g_x16);

    // one-pass fp32 -> fp16 conversions
    cvt_kernel<<<(EDIM * 2 * FDIM * HDIM / 8 + 255) / 256, 256>>>(gup, d_wgup,
        EDIM * 2 * FDIM * HDIM / 8);
    cvt_kernel<<<(EDIM * HDIM * FDIM / 8 + 255) / 256, 256>>>(dw, d_wdw,
        EDIM * HDIM * FDIM / 8);
    cvt_kernel<<<(T_TOK * HDIM / 8 + 255) / 256, 256>>>(x, d_x16,
        T_TOK * HDIM / 8);

    init_kernel<<<(PADROWS + 255) / 256, 256>>>();
    router_kernel<<<T_TOK / 4, 128>>>(x, gw, logits);
    scan_kernel<<<1, 1>>>();
    scatter_kernel<<<(T_TOK + 255) / 256, 256>>>();
    gemm1_kernel<<<dim3(PADROWS / BM, FDIM / BN), 256, smem1>>>();
    gemm2_kernel<<<dim3(PADROWS / BM, HDIM / BN), 256, smem2>>>();
    combine_kernel<<<(T_TOK * HDIM) / 256, 256>>>(out);
    (void)in_sizes; (void)n_in; (void)out_size;
}